// round 2
// baseline (speedup 1.0000x reference)
#include <cuda_runtime.h>
#include <cstdint>

#define FULL_MASK 0xFFFFFFFFu

static constexpr float EPS = 1e-10f;
static constexpr float FAR_DELTA = 1e10f;
static constexpr int P = 128;           // samples per ray
static constexpr int C = 3;             // channels
static constexpr int WARPS_PER_BLOCK = 8;

// One warp per ray, one pass. Each lane owns 4 consecutive samples.
// All global loads are LDG.128, front-batched for maximum MLP.
__global__ __launch_bounds__(256) void volume_render_kernel(
    const float* __restrict__ density,       // [N, P]
    const float* __restrict__ feature,       // [N, P, 3]
    const float* __restrict__ depth_values,  // [N, P]
    float* __restrict__ out,                 // [N*3 feat | N depth]
    int N)
{
    __shared__ float sw[WARPS_PER_BLOCK][P];   // per-warp sample weights

    const int warp = threadIdx.x >> 5;
    const int lane = threadIdx.x & 31;
    const int ray  = blockIdx.x * WARPS_PER_BLOCK + warp;
    if (ray >= N) return;

    const float4* dens4 = (const float4*)(density      + (size_t)ray * P);
    const float4* dep4  = (const float4*)(depth_values + (size_t)ray * P);
    const float4* feat4 = (const float4*)(feature      + (size_t)ray * P * C);

    // ---- front-batched wide loads (5 independent LDG.128 per lane) ----
    const float4 fv0 = feat4[lane];        // elements [0,128)   of flat feature row
    const float4 fv1 = feat4[32 + lane];   // elements [128,256)
    const float4 fv2 = feat4[64 + lane];   // elements [256,384)
    const float4 d4  = dens4[lane];        // samples lane*4 .. lane*4+3
    const float4 z4  = dep4[lane];

    // ---- deltas: 3 in-register, last one from the next lane ----
    const float znext = __shfl_down_sync(FULL_MASK, z4.x, 1);  // z[(lane+1)*4]
    const float dl0 = z4.y - z4.x;
    const float dl1 = z4.z - z4.y;
    const float dl2 = z4.w - z4.z;
    const float dl3 = (lane == 31) ? FAR_DELTA : (znext - z4.w);

    // ---- alpha / cumprod factors ----
    const float e0 = __expf(-fmaxf(d4.x, 0.0f) * dl0);
    const float e1 = __expf(-fmaxf(d4.y, 0.0f) * dl1);
    const float e2 = __expf(-fmaxf(d4.z, 0.0f) * dl2);
    const float e3 = __expf(-fmaxf(d4.w, 0.0f) * dl3);
    const float f0 = e0 + EPS, a0 = 1.0f - e0;
    const float f1 = e1 + EPS, a1 = 1.0f - e1;
    const float f2 = e2 + EPS, a2 = 1.0f - e2;
    const float f3 = e3 + EPS, a3 = 1.0f - e3;

    // per-lane exclusive prefix products
    const float pre1 = f0;
    const float pre2 = f0 * f1;
    const float pre3 = pre2 * f2;
    const float ltot = pre3 * f3;

    // ---- single warp inclusive product scan over lane totals ----
    float v = ltot;
    #pragma unroll
    for (int off = 1; off < 32; off <<= 1) {
        const float t = __shfl_up_sync(FULL_MASK, v, off);
        if (lane >= off) v *= t;
    }
    float Lex = __shfl_up_sync(FULL_MASK, v, 1);  // exclusive: product of lanes < lane
    if (lane == 0) Lex = 1.0f;

    // ---- weights ----
    const float w0 = Lex * a0;
    const float w1 = Lex * pre1 * a1;
    const float w2 = Lex * pre2 * a2;
    const float w3 = Lex * pre3 * a3;

    float acc_d = w0 * z4.x + w1 * z4.y + w2 * z4.z + w3 * z4.w;

    // publish weights for the feature pass (STS.128, conflict-free)
    *(float4*)&sw[warp][lane * 4] = make_float4(w0, w1, w2, w3);
    __syncwarp();

    // ---- feature accumulation: coalesced float4, weights from smem ----
    float acc0 = 0.0f, acc1 = 0.0f, acc2 = 0.0f;
    const float* swr = sw[warp];

    #pragma unroll
    for (int it = 0; it < 3; ++it) {
        const float4 fv = (it == 0) ? fv0 : (it == 1) ? fv1 : fv2;
        const int ebase = it * 128 + lane * 4;       // flat element index of fv.x
        const float vals[4] = {fv.x, fv.y, fv.z, fv.w};
        #pragma unroll
        for (int k = 0; k < 4; ++k) {
            const int e = ebase + k;
            const float t = swr[e / 3] * vals[k];
            const int c = e % 3;
            acc0 += (c == 0) ? t : 0.0f;
            acc1 += (c == 1) ? t : 0.0f;
            acc2 += (c == 2) ? t : 0.0f;
        }
    }

    // ---- warp reduction ----
    #pragma unroll
    for (int off = 16; off > 0; off >>= 1) {
        acc0  += __shfl_xor_sync(FULL_MASK, acc0,  off);
        acc1  += __shfl_xor_sync(FULL_MASK, acc1,  off);
        acc2  += __shfl_xor_sync(FULL_MASK, acc2,  off);
        acc_d += __shfl_xor_sync(FULL_MASK, acc_d, off);
    }

    if (lane == 0) {
        float* feat_out  = out;                     // [N, 3]
        float* depth_out = out + (size_t)N * C;     // [N]
        feat_out[(size_t)ray * C + 0] = acc0;
        feat_out[(size_t)ray * C + 1] = acc1;
        feat_out[(size_t)ray * C + 2] = acc2;
        depth_out[ray] = acc_d;
    }
}

extern "C" void kernel_launch(void* const* d_in, const int* in_sizes, int n_in,
                              void* d_out, int out_size)
{
    const float* density      = (const float*)d_in[0];
    const float* feature      = (const float*)d_in[1];
    const float* depth_values = (const float*)d_in[2];
    float* out = (float*)d_out;

    const int N = in_sizes[0] / P;   // density is [N, P]

    const int blocks = (N + WARPS_PER_BLOCK - 1) / WARPS_PER_BLOCK;
    volume_render_kernel<<<blocks, 256>>>(density, feature, depth_values, out, N);
}

// round 3
// speedup vs baseline: 1.1927x; 1.1927x over previous
#include <cuda_runtime.h>
#include <cstdint>

#define FULL_MASK 0xFFFFFFFFu

static constexpr float EPS = 1e-10f;
static constexpr float FAR_DELTA = 1e10f;
static constexpr int P = 128;           // samples per ray
static constexpr int C = 3;             // channels
static constexpr int WARPS_PER_BLOCK = 8;

// One warp per ray. Each lane owns 4 consecutive samples.
// 5 independent LDG.128 per lane, one warp product-scan, register-only
// feature dot products (compile-time channel permutation, no div/mod/smem).
__global__ __launch_bounds__(256) void volume_render_kernel(
    const float* __restrict__ density,       // [N, P]
    const float* __restrict__ feature,       // [N, P, 3]
    const float* __restrict__ depth_values,  // [N, P]
    float* __restrict__ out,                 // [N*3 feat | N depth]
    int N)
{
    const int warp = threadIdx.x >> 5;
    const int lane = threadIdx.x & 31;
    const int ray  = blockIdx.x * WARPS_PER_BLOCK + warp;
    if (ray >= N) return;

    const float4* dens4 = (const float4*)(density      + (size_t)ray * P);
    const float4* dep4  = (const float4*)(depth_values + (size_t)ray * P);
    // lane's 4 samples' features: 12 consecutive floats at lane*12
    const float4* featL = (const float4*)(feature + (size_t)ray * P * C) + lane * 3;

    // ---- front-batched independent wide loads (5 x LDG.128) ----
    const float4 d4 = dens4[lane];
    const float4 z4 = dep4[lane];
    const float4 fA = featL[0];   // s0.r s0.g s0.b s1.r
    const float4 fB = featL[1];   // s1.g s1.b s2.r s2.g
    const float4 fC = featL[2];   // s2.b s3.r s3.g s3.b

    // ---- deltas ----
    const float znext = __shfl_down_sync(FULL_MASK, z4.x, 1);  // z[(lane+1)*4]
    const float dl0 = z4.y - z4.x;
    const float dl1 = z4.z - z4.y;
    const float dl2 = z4.w - z4.z;
    const float dl3 = (lane == 31) ? FAR_DELTA : (znext - z4.w);

    // ---- alpha / cumprod factors ----
    const float e0 = __expf(-fmaxf(d4.x, 0.0f) * dl0);
    const float e1 = __expf(-fmaxf(d4.y, 0.0f) * dl1);
    const float e2 = __expf(-fmaxf(d4.z, 0.0f) * dl2);
    const float e3 = __expf(-fmaxf(d4.w, 0.0f) * dl3);
    const float f0 = e0 + EPS, a0 = 1.0f - e0;
    const float f1 = e1 + EPS, a1 = 1.0f - e1;
    const float f2 = e2 + EPS, a2 = 1.0f - e2;
    const float f3 = e3 + EPS, a3 = 1.0f - e3;

    // per-lane exclusive prefix products
    const float pre1 = f0;
    const float pre2 = f0 * f1;
    const float pre3 = pre2 * f2;
    const float ltot = pre3 * f3;

    // ---- warp inclusive product scan over lane totals ----
    float v = ltot;
    #pragma unroll
    for (int off = 1; off < 32; off <<= 1) {
        const float t = __shfl_up_sync(FULL_MASK, v, off);
        if (lane >= off) v *= t;
    }
    float Lex = __shfl_up_sync(FULL_MASK, v, 1);  // product of preceding lanes
    if (lane == 0) Lex = 1.0f;

    // ---- weights ----
    const float w0 = Lex * a0;
    const float w1 = Lex * pre1 * a1;
    const float w2 = Lex * pre2 * a2;
    const float w3 = Lex * pre3 * a3;

    // ---- register-only accumulation (fixed permutation) ----
    float acc_r = w0 * fA.x + w1 * fA.w + w2 * fB.z + w3 * fC.y;
    float acc_g = w0 * fA.y + w1 * fB.x + w2 * fB.w + w3 * fC.z;
    float acc_b = w0 * fA.z + w1 * fB.y + w2 * fC.x + w3 * fC.w;
    float acc_d = w0 * z4.x + w1 * z4.y + w2 * z4.z + w3 * z4.w;

    // ---- warp reduction ----
    #pragma unroll
    for (int off = 16; off > 0; off >>= 1) {
        acc_r += __shfl_xor_sync(FULL_MASK, acc_r, off);
        acc_g += __shfl_xor_sync(FULL_MASK, acc_g, off);
        acc_b += __shfl_xor_sync(FULL_MASK, acc_b, off);
        acc_d += __shfl_xor_sync(FULL_MASK, acc_d, off);
    }

    if (lane == 0) {
        float* feat_out  = out;                   // [N, 3]
        float* depth_out = out + (size_t)N * C;   // [N]
        feat_out[(size_t)ray * C + 0] = acc_r;
        feat_out[(size_t)ray * C + 1] = acc_g;
        feat_out[(size_t)ray * C + 2] = acc_b;
        depth_out[ray] = acc_d;
    }
}

extern "C" void kernel_launch(void* const* d_in, const int* in_sizes, int n_in,
                              void* d_out, int out_size)
{
    const float* density      = (const float*)d_in[0];
    const float* feature      = (const float*)d_in[1];
    const float* depth_values = (const float*)d_in[2];
    float* out = (float*)d_out;

    const int N = in_sizes[0] / P;   // density is [N, P]

    const int blocks = (N + WARPS_PER_BLOCK - 1) / WARPS_PER_BLOCK;
    volume_render_kernel<<<blocks, 256>>>(density, feature, depth_values, out, N);
}